// round 2
// baseline (speedup 1.0000x reference)
#include <cuda_runtime.h>
#include <math.h>

#define NN 65535            // total nodes
#define LEAF_START 32767
#define NMEM 256

// ---- scratch (device globals; no allocation allowed) ----
__device__ float g_PRE[(size_t)NN * 1024];     // [N,1024]: cols 0..767 = x@W_ioux^T, 768..1023 = x@W_fx^T
__device__ float g_P[(size_t)16384 * 1280];    // per-level GEMM output [S,1280]
__device__ float g_WT1[300 * 1024];            // transposed combined input weights [K=300][1024]
__device__ float g_WT2[512 * 1280];            // transposed combined recurrent weights [K=512][1280]

// ---- weight repacking ----
__global__ void build_wt1(const float* __restrict__ W_ioux, const float* __restrict__ W_fx) {
    int idx = blockIdx.x * blockDim.x + threadIdx.x;
    if (idx >= 300 * 1024) return;
    int k = idx >> 10;        // 0..299
    int j = idx & 1023;       // 0..1023
    g_WT1[idx] = (j < 768) ? W_ioux[j * 300 + k] : W_fx[(j - 768) * 300 + k];
}

__global__ void build_wt2(const float* __restrict__ W_iouh, const float* __restrict__ W_fh) {
    int idx = blockIdx.x * blockDim.x + threadIdx.x;
    if (idx >= 512 * 1280) return;
    int k = idx / 1280;       // 0..511
    int j = idx - k * 1280;   // 0..1279
    float v;
    if (j < 768)            v = W_iouh[j * 256 + (k & 255)];              // iou: sees hl+hr
    else if (j < 1024)      v = (k < 256) ? W_fh[(j - 768) * 256 + k] : 0.f;      // fl: hl only
    else                    v = (k >= 256) ? W_fh[(j - 1024) * 256 + (k - 256)] : 0.f; // fr: hr only
    g_WT2[idx] = v;
}

// ---- fp32 tiled GEMM: C[M,Nc] = A[M,K](row-major, lda) * B[K,Nc](row-major, ldb) ----
// BM=BN=128, BK=16, 256 threads, 8x8 microtile per thread.
__global__ __launch_bounds__(256)
void gemm128(const float* __restrict__ A, int M, int K, int lda,
             const float* __restrict__ B, int ldb,
             float* __restrict__ C, int ldc) {
    __shared__ float As[16][132];   // transposed A tile, padded
    __shared__ float Bs[16][128];

    const int tid = threadIdx.x;
    const int tx = tid & 15, ty = tid >> 4;
    const int bm = blockIdx.x * 128, bn = blockIdx.y * 128;

    float acc[8][8];
#pragma unroll
    for (int i = 0; i < 8; i++)
#pragma unroll
        for (int j = 0; j < 8; j++) acc[i][j] = 0.f;

    const int arow = tid >> 1;          // 0..127
    const int ak8  = (tid & 1) * 8;     // 0 or 8
    const int bkk  = tid >> 4;          // 0..15
    const int bcol = (tid & 15) * 8;    // 0..120

    for (int k0 = 0; k0 < K; k0 += 16) {
        // A tile load (scalar, guarded) with transpose into As[k][m]
        {
            float v[8];
            const int gr = bm + arow;
            const bool rok = gr < M;
            const float* p = A + (size_t)gr * lda + k0 + ak8;
#pragma unroll
            for (int u = 0; u < 8; u++)
                v[u] = (rok && (k0 + ak8 + u) < K) ? p[u] : 0.f;
#pragma unroll
            for (int u = 0; u < 8; u++) As[ak8 + u][arow] = v[u];
        }
        // B tile load (vectorized, guarded on k)
        {
            float4 b0 = make_float4(0.f, 0.f, 0.f, 0.f), b1 = b0;
            if (k0 + bkk < K) {
                const float* p = B + (size_t)(k0 + bkk) * ldb + bn + bcol;
                b0 = *(const float4*)p;
                b1 = *(const float4*)(p + 4);
            }
            *(float4*)&Bs[bkk][bcol]     = b0;
            *(float4*)&Bs[bkk][bcol + 4] = b1;
        }
        __syncthreads();
#pragma unroll
        for (int kk = 0; kk < 16; kk++) {
            float a[8], b[8];
            *(float4*)&a[0] = *(const float4*)&As[kk][ty * 4];
            *(float4*)&a[4] = *(const float4*)&As[kk][64 + ty * 4];
            *(float4*)&b[0] = *(const float4*)&Bs[kk][tx * 4];
            *(float4*)&b[4] = *(const float4*)&Bs[kk][64 + tx * 4];
#pragma unroll
            for (int i = 0; i < 8; i++)
#pragma unroll
                for (int j = 0; j < 8; j++)
                    acc[i][j] = fmaf(a[i], b[j], acc[i][j]);
        }
        __syncthreads();
    }
    // store: rows ty*4+i / 64+ty*4+i, cols tx*4.. / 64+tx*4..
#pragma unroll
    for (int i = 0; i < 8; i++) {
        const int r = bm + ((i < 4) ? (ty * 4 + i) : (64 + ty * 4 + (i - 4)));
        if (r < M) {
            float* cp = C + (size_t)r * ldc + bn;
            float4 lo = make_float4(acc[i][0], acc[i][1], acc[i][2], acc[i][3]);
            float4 hi = make_float4(acc[i][4], acc[i][5], acc[i][6], acc[i][7]);
            *(float4*)(cp + tx * 4)      = lo;
            *(float4*)(cp + 64 + tx * 4) = hi;
        }
    }
}

// ---- epilogues ----
__device__ __forceinline__ float sigmoidf_(float x) { return 1.f / (1.f + __expf(-x)); }

__global__ void leaf_epi(float* __restrict__ c, float* __restrict__ h,
                         const float* __restrict__ b_ioux, const float* __restrict__ b_iouh) {
    const int n = LEAF_START + blockIdx.x;      // 32767..65534
    const int m = threadIdx.x;
    const float* pre = g_PRE + (size_t)n * 1024;
    const float iv = sigmoidf_(pre[m]       + b_ioux[m]       + b_iouh[m]);
    const float ov = sigmoidf_(pre[256 + m] + b_ioux[256 + m] + b_iouh[256 + m]);
    const float uv = tanhf(    pre[512 + m] + b_ioux[512 + m] + b_iouh[512 + m]);
    const float cn = iv * uv;
    const float hn = ov * tanhf(cn);
    c[(size_t)n * NMEM + m] = cn;
    h[(size_t)n * NMEM + m] = hn;
}

__global__ void level_epi(float* __restrict__ c, float* __restrict__ h,
                          int start, int sc,
                          const float* __restrict__ b_ioux, const float* __restrict__ b_iouh,
                          const float* __restrict__ b_fx, const float* __restrict__ b_fh) {
    const int r = blockIdx.x;
    const int n = start + r;
    const int m = threadIdx.x;
    const float* p   = g_P   + (size_t)r * 1280;
    const float* pre = g_PRE + (size_t)n * 1024;
    const float fxv = pre[768 + m] + b_fx[m] + b_fh[m];   // fx_x + b_fh (shared by fl, fr)
    const float iv = sigmoidf_(p[m]        + pre[m]        + b_ioux[m]        + b_iouh[m]);
    const float ov = sigmoidf_(p[256 + m]  + pre[256 + m]  + b_ioux[256 + m]  + b_iouh[256 + m]);
    const float uv = tanhf(    p[512 + m]  + pre[512 + m]  + b_ioux[512 + m]  + b_iouh[512 + m]);
    const float fl = sigmoidf_(p[768 + m]  + fxv);
    const float fr = sigmoidf_(p[1024 + m] + fxv);
    const int lc = sc + 2 * r;
    const float cl = c[(size_t)lc * NMEM + m];
    const float cr = c[(size_t)(lc + 1) * NMEM + m];
    const float cn = iv * uv + fl * cl + fr * cr;
    const float hn = ov * tanhf(cn);
    c[(size_t)n * NMEM + m] = cn;
    h[(size_t)n * NMEM + m] = hn;
}

// ---- launcher ----
extern "C" void kernel_launch(void* const* d_in, const int* in_sizes, int n_in,
                              void* d_out, int out_size) {
    const float* inputs = (const float*)d_in[0];
    const float* W_ioux = (const float*)d_in[1];
    const float* b_ioux = (const float*)d_in[2];
    const float* W_iouh = (const float*)d_in[3];
    const float* b_iouh = (const float*)d_in[4];
    const float* W_fx   = (const float*)d_in[5];
    const float* b_fx   = (const float*)d_in[6];
    const float* W_fh   = (const float*)d_in[7];
    const float* b_fh   = (const float*)d_in[8];
    (void)in_sizes; (void)n_in; (void)out_size;

    float* c = (float*)d_out;                   // out[0] = c  [N,256]
    float* h = c + (size_t)NN * NMEM;           // out[1] = h  [N,256]

    float *pPRE, *pP, *pWT1, *pWT2;
    cudaGetSymbolAddress((void**)&pPRE, g_PRE);
    cudaGetSymbolAddress((void**)&pP,   g_P);
    cudaGetSymbolAddress((void**)&pWT1, g_WT1);
    cudaGetSymbolAddress((void**)&pWT2, g_WT2);

    build_wt1<<<(300 * 1024 + 255) / 256, 256>>>(W_ioux, W_fx);
    build_wt2<<<(512 * 1280 + 255) / 256, 256>>>(W_iouh, W_fh);

    // Precompute input-side projections for ALL nodes: g_PRE = inputs @ [W_ioux|W_fx]^T
    {
        dim3 g((NN + 127) / 128, 1024 / 128);
        gemm128<<<g, 256>>>(inputs, NN, 300, 300, pWT1, 1024, pPRE, 1024);
    }

    // Leaves (depth 15): children are zero
    leaf_epi<<<32768, 256>>>(c, h, b_ioux, b_iouh);

    // Internal levels, bottom-up. Children of level d are contiguous: A = h[sc..sc+2S) viewed [S,512].
    for (int d = 14; d >= 0; --d) {
        const int S = 1 << d;
        const int start = S - 1;
        const int sc = 2 * S - 1;
        const float* A = h + (size_t)sc * NMEM;     // [S, 512] = [hl | hr]
        dim3 g((S + 127) / 128, 1280 / 128);
        gemm128<<<g, 256>>>(A, S, 512, 512, pWT2, 1280, pP, 1280);
        level_epi<<<S, 256>>>(c, h, start, sc, b_ioux, b_iouh, b_fx, b_fh);
    }
}

// round 4
// speedup vs baseline: 3.2253x; 3.2253x over previous
#include <cuda_runtime.h>
#include <math.h>
#include <cstdint>

#define NN 65535            // total nodes
#define LEAF_START 32767
#define NMEM 256

// ---- scratch (device globals; no allocation allowed) ----
__device__ float g_PRE[(size_t)NN * 1024];     // [N,1024]: 0..767 = x@W_ioux^T, 768..1023 = x@W_fx^T
__device__ float g_P[(size_t)16384 * 1280];    // per-level GEMM output [S,1280]
__device__ float g_W1[1024 * 320];             // B for gemm1: [n=1024][k=320] (K padded 300->320, tf32-rounded)
__device__ float g_W2[1280 * 512];             // B for gemm2: [n=1280][k=512] (tf32-rounded)

// ============================ helpers ============================
__device__ __forceinline__ uint32_t smem_u32(const void* p) {
    uint32_t a;
    asm("{ .reg .u64 t; cvta.to.shared.u64 t, %1; cvt.u32.u64 %0, t; }" : "=r"(a) : "l"(p));
    return a;
}
__device__ __forceinline__ float tf32_rna(float v) {
    uint32_t t;
    asm("cvt.rna.tf32.f32 %0, %1;" : "=r"(t) : "f"(v));
    return __uint_as_float(t);
}
__device__ __forceinline__ uint32_t tf32_rna_u(float v) {
    uint32_t t;
    asm("cvt.rna.tf32.f32 %0, %1;" : "=r"(t) : "f"(v));
    return t;
}

// ============================ weight repacking (pre-rounded to tf32) ============================
__global__ void build_w1(const float* __restrict__ W_ioux, const float* __restrict__ W_fx) {
    int idx = blockIdx.x * blockDim.x + threadIdx.x;
    if (idx >= 1024 * 320) return;
    int j = idx / 320, k = idx - j * 320;
    float v = 0.f;
    if (k < 300) v = (j < 768) ? W_ioux[j * 300 + k] : W_fx[(j - 768) * 300 + k];
    g_W1[idx] = tf32_rna(v);
}

__global__ void build_w2(const float* __restrict__ W_iouh, const float* __restrict__ W_fh) {
    int idx = blockIdx.x * blockDim.x + threadIdx.x;
    if (idx >= 1280 * 512) return;
    int j = idx >> 9, k = idx & 511;
    float v;
    if (j < 768)       v = W_iouh[j * 256 + (k & 255)];
    else if (j < 1024) v = (k < 256) ? W_fh[(j - 768) * 256 + k] : 0.f;
    else               v = (k >= 256) ? W_fh[(j - 1024) * 256 + (k - 256)] : 0.f;
    g_W2[idx] = tf32_rna(v);
}

// ============================ tf32 mma.sync GEMM ============================
// C[M,Nc] = A[M,K] * B[Nc,K]^T.  CTA tile 128x128, BK=32, 256 threads (8 warps),
// warp tile 32x64 (2 m-tiles of 16, 8 n-tiles of 8). 2-stage cp.async double buffer.
// Smem tiles stored [row][32+4 floats] -> conflict-free fragment loads.

#define SROW 36                      // 32 + 4 pad floats per smem row
#define STAGE_FLOATS (2 * 128 * SROW) // A tile + B tile per stage

__device__ __forceinline__ void load_stage(float* As, float* Bs,
                                           const float* __restrict__ A, int M, int lda, int avalid_bytes,
                                           const float* __restrict__ B, int ldb,
                                           int bm, int bn, int k0, int tid) {
    const int r0 = tid >> 3;
    const int kq = (tid & 7) * 4;
#pragma unroll
    for (int i = 0; i < 4; i++) {
        const int row = r0 + i * 32;
        // A (guarded rows + ragged K -> zfill)
        {
            const bool ok = (bm + row < M) && ((k0 + kq) * 4 < avalid_bytes);
            const float* ga = ok ? (A + (size_t)(bm + row) * lda + k0 + kq) : A;
            uint32_t sa = smem_u32(As + row * SROW + kq);
            uint32_t sz = ok ? 16u : 0u;
            asm volatile("cp.async.cg.shared.global [%0], [%1], 16, %2;"
                         :: "r"(sa), "l"(ga), "r"(sz) : "memory");
        }
        // B (fully padded weights; no guard needed)
        {
            const float* gb = B + (size_t)(bn + row) * ldb + k0 + kq;
            uint32_t sb = smem_u32(Bs + row * SROW + kq);
            asm volatile("cp.async.cg.shared.global [%0], [%1], 16;"
                         :: "r"(sb), "l"(gb) : "memory");
        }
    }
}

__global__ __launch_bounds__(256, 2)
void gemm_mma(const float* __restrict__ A, int M, int lda, int avalid_bytes,
              const float* __restrict__ B, int ldb,
              float* __restrict__ C, int ldc, int KC) {
    extern __shared__ float smem[];

    const int tid  = threadIdx.x;
    const int wid  = tid >> 5;
    const int lane = tid & 31;
    const int wm = wid & 3;          // 0..3 : warp row (32 rows each)
    const int wn = wid >> 2;         // 0..1 : warp col (64 cols each)
    const int g  = lane >> 2;        // group id 0..7
    const int c4 = lane & 3;         // thread-in-group 0..3
    const int bm = blockIdx.x * 128;
    const int bn = blockIdx.y * 128;

    float acc[2][8][4];
#pragma unroll
    for (int mt = 0; mt < 2; mt++)
#pragma unroll
        for (int nt = 0; nt < 8; nt++)
#pragma unroll
            for (int i = 0; i < 4; i++) acc[mt][nt][i] = 0.f;

    // prologue
    load_stage(smem, smem + 128 * SROW, A, M, lda, avalid_bytes, B, ldb, bm, bn, 0, tid);
    asm volatile("cp.async.commit_group;" ::: "memory");

    for (int ci = 0; ci < KC; ci++) {
        if (ci + 1 < KC) {
            float* As = smem + (size_t)((ci + 1) & 1) * STAGE_FLOATS;
            load_stage(As, As + 128 * SROW, A, M, lda, avalid_bytes, B, ldb, bm, bn, (ci + 1) * 32, tid);
            asm volatile("cp.async.commit_group;" ::: "memory");
            asm volatile("cp.async.wait_group 1;" ::: "memory");
        } else {
            asm volatile("cp.async.wait_group 0;" ::: "memory");
        }
        __syncthreads();

        const float* As = smem + (size_t)(ci & 1) * STAGE_FLOATS;
        const float* Bs = As + 128 * SROW;

#pragma unroll
        for (int kt = 0; kt < 4; kt++) {
            const int kk = kt * 8 + c4;
            // A fragments (cvt.rna to tf32 in-register)
            uint32_t a[2][4];
#pragma unroll
            for (int mt = 0; mt < 2; mt++) {
                const int row = wm * 32 + mt * 16 + g;
                a[mt][0] = tf32_rna_u(As[row * SROW + kk]);
                a[mt][1] = tf32_rna_u(As[(row + 8) * SROW + kk]);
                a[mt][2] = tf32_rna_u(As[row * SROW + kk + 4]);
                a[mt][3] = tf32_rna_u(As[(row + 8) * SROW + kk + 4]);
            }
            // B fragments (pre-rounded in global)
            uint32_t b[8][2];
#pragma unroll
            for (int nt = 0; nt < 8; nt++) {
                const int nrow = wn * 64 + nt * 8 + g;
                b[nt][0] = __float_as_uint(Bs[nrow * SROW + kk]);
                b[nt][1] = __float_as_uint(Bs[nrow * SROW + kk + 4]);
            }
#pragma unroll
            for (int mt = 0; mt < 2; mt++)
#pragma unroll
                for (int nt = 0; nt < 8; nt++) {
                    asm volatile(
                        "mma.sync.aligned.m16n8k8.row.col.f32.tf32.tf32.f32 "
                        "{%0,%1,%2,%3}, {%4,%5,%6,%7}, {%8,%9}, {%0,%1,%2,%3};"
                        : "+f"(acc[mt][nt][0]), "+f"(acc[mt][nt][1]),
                          "+f"(acc[mt][nt][2]), "+f"(acc[mt][nt][3])
                        : "r"(a[mt][0]), "r"(a[mt][1]), "r"(a[mt][2]), "r"(a[mt][3]),
                          "r"(b[nt][0]), "r"(b[nt][1]));
                }
        }
        __syncthreads();
    }

    // store
#pragma unroll
    for (int mt = 0; mt < 2; mt++) {
        const int row = bm + wm * 32 + mt * 16 + g;
#pragma unroll
        for (int nt = 0; nt < 8; nt++) {
            const int col = bn + wn * 64 + nt * 8 + 2 * c4;
            if (row < M)
                *(float2*)&C[(size_t)row * ldc + col] =
                    make_float2(acc[mt][nt][0], acc[mt][nt][1]);
            if (row + 8 < M)
                *(float2*)&C[(size_t)(row + 8) * ldc + col] =
                    make_float2(acc[mt][nt][2], acc[mt][nt][3]);
        }
    }
}

// ============================ epilogues ============================
__device__ __forceinline__ float sigmoidf_(float x) {
    return __fdividef(1.f, 1.f + __expf(-x));
}
__device__ __forceinline__ float ftanh_(float x) {
    float t = __expf(2.f * x);
    return 1.f - __fdividef(2.f, t + 1.f);
}

__global__ void leaf_epi(float* __restrict__ c, float* __restrict__ h,
                         const float* __restrict__ b_ioux, const float* __restrict__ b_iouh) {
    const int n = LEAF_START + blockIdx.x;      // 32767..65534
    const int m = threadIdx.x;
    const float* pre = g_PRE + (size_t)n * 1024;
    const float iv = sigmoidf_(pre[m]       + b_ioux[m]       + b_iouh[m]);
    const float ov = sigmoidf_(pre[256 + m] + b_ioux[256 + m] + b_iouh[256 + m]);
    const float uv = ftanh_(   pre[512 + m] + b_ioux[512 + m] + b_iouh[512 + m]);
    const float cn = iv * uv;
    const float hn = ov * ftanh_(cn);
    c[(size_t)n * NMEM + m] = cn;
    h[(size_t)n * NMEM + m] = hn;
}

__global__ void level_epi(float* __restrict__ c, float* __restrict__ h,
                          int start, int sc,
                          const float* __restrict__ b_ioux, const float* __restrict__ b_iouh,
                          const float* __restrict__ b_fx, const float* __restrict__ b_fh) {
    const int r = blockIdx.x;
    const int n = start + r;
    const int m = threadIdx.x;
    const float* p   = g_P   + (size_t)r * 1280;
    const float* pre = g_PRE + (size_t)n * 1024;
    const float fxv = pre[768 + m] + b_fx[m] + b_fh[m];
    const float iv = sigmoidf_(p[m]        + pre[m]        + b_ioux[m]        + b_iouh[m]);
    const float ov = sigmoidf_(p[256 + m]  + pre[256 + m]  + b_ioux[256 + m]  + b_iouh[256 + m]);
    const float uv = ftanh_(   p[512 + m]  + pre[512 + m]  + b_ioux[512 + m]  + b_iouh[512 + m]);
    const float fl = sigmoidf_(p[768 + m]  + fxv);
    const float fr = sigmoidf_(p[1024 + m] + fxv);
    const int lc = sc + 2 * r;
    const float cl = c[(size_t)lc * NMEM + m];
    const float cr = c[(size_t)(lc + 1) * NMEM + m];
    const float cn = iv * uv + fl * cl + fr * cr;
    const float hn = ov * ftanh_(cn);
    c[(size_t)n * NMEM + m] = cn;
    h[(size_t)n * NMEM + m] = hn;
}

// ============================ launcher ============================
extern "C" void kernel_launch(void* const* d_in, const int* in_sizes, int n_in,
                              void* d_out, int out_size) {
    const float* inputs = (const float*)d_in[0];
    const float* W_ioux = (const float*)d_in[1];
    const float* b_ioux = (const float*)d_in[2];
    const float* W_iouh = (const float*)d_in[3];
    const float* b_iouh = (const float*)d_in[4];
    const float* W_fx   = (const float*)d_in[5];
    const float* b_fx   = (const float*)d_in[6];
    const float* W_fh   = (const float*)d_in[7];
    const float* b_fh   = (const float*)d_in[8];
    (void)in_sizes; (void)n_in; (void)out_size;

    float* c = (float*)d_out;                   // out[0] = c  [N,256]
    float* h = c + (size_t)NN * NMEM;           // out[1] = h  [N,256]

    float *pPRE, *pP, *pW1, *pW2;
    cudaGetSymbolAddress((void**)&pPRE, g_PRE);
    cudaGetSymbolAddress((void**)&pP,   g_P);
    cudaGetSymbolAddress((void**)&pW1,  g_W1);
    cudaGetSymbolAddress((void**)&pW2,  g_W2);

    const int SMEM_BYTES = 2 * STAGE_FLOATS * 4;   // 73728 bytes
    cudaFuncSetAttribute(gemm_mma, cudaFuncAttributeMaxDynamicSharedMemorySize, SMEM_BYTES);

    build_w1<<<(1024 * 320 + 255) / 256, 256>>>(W_ioux, W_fx);
    build_w2<<<(1280 * 512 + 255) / 256, 256>>>(W_iouh, W_fh);

    // gemm1: PRE = inputs @ [W_ioux|W_fx]^T   (M=65535, K=300 (pad 320), N=1024)
    {
        dim3 g((NN + 127) / 128, 1024 / 128);
        gemm_mma<<<g, 256, SMEM_BYTES>>>(inputs, NN, 300, 1200, pW1, 320, pPRE, 1024, 10);
    }

    // leaves (depth 15)
    leaf_epi<<<32768, 256>>>(c, h, b_ioux, b_iouh);

    // internal levels bottom-up; children contiguous: A = h[sc..sc+2S) viewed [S,512]
    for (int d = 14; d >= 0; --d) {
        const int S = 1 << d;
        const int start = S - 1;
        const int sc = 2 * S - 1;
        const float* A = h + (size_t)sc * NMEM;     // [S, 512]
        dim3 g((S + 127) / 128, 1280 / 128);
        gemm_mma<<<g, 256, SMEM_BYTES>>>(A, S, 512, 2048, pW2, 512, pP, 1280, 16);
        level_epi<<<S, 256>>>(c, h, start, sc, b_ioux, b_iouh, b_fx, b_fh);
    }
}

// round 5
// speedup vs baseline: 4.0767x; 1.2640x over previous
#include <cuda_runtime.h>
#include <math.h>
#include <cstdint>

#define NN 65535            // total nodes
#define LEAF_START 32767
#define NMEM 256

// ---- scratch (device globals; no allocation allowed) ----
__device__ float g_PRE[(size_t)NN * 1024];      // [N,1024]: 0..767 x@W_ioux^T, 768..1023 x@W_fx^T
__device__ float g_PIOU[(size_t)16384 * 768];   // per-level iou recurrent term [S,768]
__device__ float g_PF[(size_t)32768 * 256];     // per-level child f-projections [2S,256]
__device__ float g_W1[1024 * 320];              // gemm1 B: [n=1024][k=320] tf32-rounded, K padded
__device__ float g_WIOU[768 * 256];             // W_iouh tf32-rounded [n][k]
__device__ float g_WF[256 * 256];               // W_fh tf32-rounded [n][k]
__device__ float g_BIO[768];                    // b_ioux + b_iouh
__device__ float g_BF[256];                     // b_fx + b_fh

// ============================ helpers ============================
__device__ __forceinline__ uint32_t smem_u32(const void* p) {
    uint32_t a;
    asm("{ .reg .u64 t; cvta.to.shared.u64 t, %1; cvt.u32.u64 %0, t; }" : "=r"(a) : "l"(p));
    return a;
}
__device__ __forceinline__ float tf32_rna(float v) {
    uint32_t t;
    asm("cvt.rna.tf32.f32 %0, %1;" : "=r"(t) : "f"(v));
    return __uint_as_float(t);
}
__device__ __forceinline__ uint32_t tf32_rna_u(float v) {
    uint32_t t;
    asm("cvt.rna.tf32.f32 %0, %1;" : "=r"(t) : "f"(v));
    return t;
}

// ============================ weight repacking ============================
__global__ void build_w1(const float* __restrict__ W_ioux, const float* __restrict__ W_fx) {
    int idx = blockIdx.x * blockDim.x + threadIdx.x;
    if (idx >= 1024 * 320) return;
    int j = idx / 320, k = idx - j * 320;
    float v = 0.f;
    if (k < 300) v = (j < 768) ? W_ioux[j * 300 + k] : W_fx[(j - 768) * 300 + k];
    g_W1[idx] = tf32_rna(v);
}

__global__ void build_misc(const float* __restrict__ W_iouh, const float* __restrict__ W_fh,
                           const float* __restrict__ b_ioux, const float* __restrict__ b_iouh,
                           const float* __restrict__ b_fx, const float* __restrict__ b_fh) {
    int i = blockIdx.x * blockDim.x + threadIdx.x;
    if (i < 196608)       g_WIOU[i] = tf32_rna(W_iouh[i]);
    else if (i < 262144)  g_WF[i - 196608] = tf32_rna(W_fh[i - 196608]);
    else if (i < 262912)  { int j = i - 262144; g_BIO[j] = b_ioux[j] + b_iouh[j]; }
    else if (i < 263168)  { int j = i - 262912; g_BF[j]  = b_fx[j]  + b_fh[j];  }
}

// ============================ shared mma compute core ============================
#define SROW 36                        // 32 + 4 pad floats per smem row
#define STAGE_FLOATS (2 * 128 * SROW)  // A tile + B tile per stage

#define MMA_COMPUTE(As, Bs)                                                            \
    do {                                                                               \
        _Pragma("unroll")                                                              \
        for (int kt = 0; kt < 4; kt++) {                                               \
            const int kk = kt * 8 + c4;                                                \
            uint32_t a[2][4];                                                          \
            _Pragma("unroll")                                                          \
            for (int mt = 0; mt < 2; mt++) {                                           \
                const int row = wm * 32 + mt * 16 + g;                                 \
                a[mt][0] = tf32_rna_u((As)[row * SROW + kk]);                          \
                a[mt][1] = tf32_rna_u((As)[(row + 8) * SROW + kk]);                    \
                a[mt][2] = tf32_rna_u((As)[row * SROW + kk + 4]);                      \
                a[mt][3] = tf32_rna_u((As)[(row + 8) * SROW + kk + 4]);                \
            }                                                                          \
            uint32_t b[8][2];                                                          \
            _Pragma("unroll")                                                          \
            for (int nt = 0; nt < 8; nt++) {                                           \
                const int nrow = wn * 64 + nt * 8 + g;                                 \
                b[nt][0] = __float_as_uint((Bs)[nrow * SROW + kk]);                    \
                b[nt][1] = __float_as_uint((Bs)[nrow * SROW + kk + 4]);                \
            }                                                                          \
            _Pragma("unroll")                                                          \
            for (int mt = 0; mt < 2; mt++)                                             \
                _Pragma("unroll")                                                      \
                for (int nt = 0; nt < 8; nt++) {                                       \
                    asm volatile(                                                      \
                        "mma.sync.aligned.m16n8k8.row.col.f32.tf32.tf32.f32 "          \
                        "{%0,%1,%2,%3}, {%4,%5,%6,%7}, {%8,%9}, {%0,%1,%2,%3};"        \
                        : "+f"(acc[mt][nt][0]), "+f"(acc[mt][nt][1]),                  \
                          "+f"(acc[mt][nt][2]), "+f"(acc[mt][nt][3])                   \
                        : "r"(a[mt][0]), "r"(a[mt][1]), "r"(a[mt][2]), "r"(a[mt][3]),  \
                          "r"(b[nt][0]), "r"(b[nt][1]));                               \
                }                                                                      \
        }                                                                              \
    } while (0)

// ============================ gemm1: cp.async pipelined, A raw fp32 ============================
__device__ __forceinline__ void load_stage(float* As, float* Bs,
                                           const float* __restrict__ A, int M, int lda, int avalid_bytes,
                                           const float* __restrict__ B, int ldb,
                                           int bm, int bn, int k0, int tid) {
    const int r0 = tid >> 3;
    const int kq = (tid & 7) * 4;
#pragma unroll
    for (int i = 0; i < 4; i++) {
        const int row = r0 + i * 32;
        {
            const bool ok = (bm + row < M) && ((k0 + kq) * 4 < avalid_bytes);
            const float* ga = ok ? (A + (size_t)(bm + row) * lda + k0 + kq) : A;
            uint32_t sa = smem_u32(As + row * SROW + kq);
            uint32_t sz = ok ? 16u : 0u;
            asm volatile("cp.async.cg.shared.global [%0], [%1], 16, %2;"
                         :: "r"(sa), "l"(ga), "r"(sz) : "memory");
        }
        {
            const float* gb = B + (size_t)(bn + row) * ldb + k0 + kq;
            uint32_t sb = smem_u32(Bs + row * SROW + kq);
            asm volatile("cp.async.cg.shared.global [%0], [%1], 16;"
                         :: "r"(sb), "l"(gb) : "memory");
        }
    }
}

__global__ __launch_bounds__(256, 2)
void gemm_mma(const float* __restrict__ A, int M, int lda, int avalid_bytes,
              const float* __restrict__ B, int ldb,
              float* __restrict__ C, int ldc, int KC) {
    extern __shared__ float smem[];

    const int tid  = threadIdx.x;
    const int wid  = tid >> 5;
    const int lane = tid & 31;
    const int wm = wid & 3, wn = wid >> 2;
    const int g  = lane >> 2, c4 = lane & 3;
    // column-major CTA order: all column tiles of a row-block run consecutively (A stays L2-hot)
    const int bm = blockIdx.y * 128;
    const int bn = blockIdx.x * 128;

    float acc[2][8][4];
#pragma unroll
    for (int mt = 0; mt < 2; mt++)
#pragma unroll
        for (int nt = 0; nt < 8; nt++)
#pragma unroll
            for (int i = 0; i < 4; i++) acc[mt][nt][i] = 0.f;

    load_stage(smem, smem + 128 * SROW, A, M, lda, avalid_bytes, B, ldb, bm, bn, 0, tid);
    asm volatile("cp.async.commit_group;" ::: "memory");

    for (int ci = 0; ci < KC; ci++) {
        if (ci + 1 < KC) {
            float* As = smem + (size_t)((ci + 1) & 1) * STAGE_FLOATS;
            load_stage(As, As + 128 * SROW, A, M, lda, avalid_bytes, B, ldb, bm, bn, (ci + 1) * 32, tid);
            asm volatile("cp.async.commit_group;" ::: "memory");
            asm volatile("cp.async.wait_group 1;" ::: "memory");
        } else {
            asm volatile("cp.async.wait_group 0;" ::: "memory");
        }
        __syncthreads();
        const float* As = smem + (size_t)(ci & 1) * STAGE_FLOATS;
        const float* Bs = As + 128 * SROW;
        MMA_COMPUTE(As, Bs);
        __syncthreads();
    }

#pragma unroll
    for (int mt = 0; mt < 2; mt++) {
        const int row = bm + wm * 32 + mt * 16 + g;
#pragma unroll
        for (int nt = 0; nt < 8; nt++) {
            const int col = bn + wn * 64 + nt * 8 + 2 * c4;
            if (row < M)
                *(float2*)&C[(size_t)row * ldc + col] = make_float2(acc[mt][nt][0], acc[mt][nt][1]);
            if (row + 8 < M)
                *(float2*)&C[(size_t)(row + 8) * ldc + col] = make_float2(acc[mt][nt][2], acc[mt][nt][3]);
        }
    }
}

// ============================ merged per-level GEMM ============================
// Tile types flattened in grid.x:
//   t < tiles_m_iou*6 : iou tile -> A[r][k] = h[sc+2m] + h[sc+2m+1], B = g_WIOU, C = g_PIOU (ldc 768)
//   else              : f tile   -> A[m][k] = h[sc+m],               B = g_WF,   C = g_PF   (ldc 256)
// K = 256 (8 chunks). A register-staged, B via cp.async.
__global__ __launch_bounds__(256)
void level_gemm(const float* __restrict__ hbase, int S,
                const float* __restrict__ WIOU, const float* __restrict__ WF,
                float* __restrict__ PIOU, float* __restrict__ PF, int tiles_m_iou) {
    extern __shared__ float smem[];

    const int tid  = threadIdx.x;
    const int wid  = tid >> 5;
    const int lane = tid & 31;
    const int wm = wid & 3, wn = wid >> 2;
    const int g  = lane >> 2, c4 = lane & 3;

    int t = blockIdx.x;
    const bool is_iou = (t < tiles_m_iou * 6);
    int tm, tn, Mrows, ldc;
    const float* Bsrc;
    float* C;
    if (is_iou) { tm = t / 6; tn = t - tm * 6; Mrows = S;     Bsrc = WIOU + (size_t)tn * 128 * 256; C = PIOU; ldc = 768; }
    else { int t2 = t - tiles_m_iou * 6; tm = t2 >> 1; tn = t2 & 1; Mrows = 2 * S; Bsrc = WF + (size_t)tn * 128 * 256; C = PF; ldc = 256; }
    const int bm = tm * 128;

    const int r0 = tid >> 3;          // 0..31
    const int kq = (tid & 7) * 4;     // 0..28

    float acc[2][8][4];
#pragma unroll
    for (int mt = 0; mt < 2; mt++)
#pragma unroll
        for (int nt = 0; nt < 8; nt++)
#pragma unroll
            for (int i = 0; i < 4; i++) acc[mt][nt][i] = 0.f;

    float4 ra[4], ra2[4];
    const float4 z4 = make_float4(0.f, 0.f, 0.f, 0.f);

#define LG_LOAD_A(ci)                                                                     \
    do {                                                                                  \
        const int k0 = (ci) * 32;                                                         \
        _Pragma("unroll")                                                                 \
        for (int i = 0; i < 4; i++) {                                                     \
            const int m = bm + r0 + i * 32;                                               \
            if (is_iou) {                                                                 \
                if (m < S) {                                                              \
                    ra[i]  = *(const float4*)&hbase[(size_t)(2 * m) * 256 + k0 + kq];     \
                    ra2[i] = *(const float4*)&hbase[(size_t)(2 * m + 1) * 256 + k0 + kq]; \
                } else { ra[i] = z4; ra2[i] = z4; }                                       \
            } else {                                                                      \
                ra[i] = (m < Mrows) ? *(const float4*)&hbase[(size_t)m * 256 + k0 + kq]   \
                                    : z4;                                                 \
            }                                                                             \
        }                                                                                 \
    } while (0)

#define LG_CPASYNC_B(ci, Bs)                                                              \
    do {                                                                                  \
        const int k0 = (ci) * 32;                                                         \
        _Pragma("unroll")                                                                 \
        for (int i = 0; i < 4; i++) {                                                     \
            const int row = r0 + i * 32;                                                  \
            const float* gb = Bsrc + (size_t)row * 256 + k0 + kq;                         \
            uint32_t sb = smem_u32((Bs) + row * SROW + kq);                               \
            asm volatile("cp.async.cg.shared.global [%0], [%1], 16;"                      \
                         :: "r"(sb), "l"(gb) : "memory");                                 \
        }                                                                                 \
    } while (0)

#define LG_STORE_A(As)                                                                    \
    do {                                                                                  \
        _Pragma("unroll")                                                                 \
        for (int i = 0; i < 4; i++) {                                                     \
            const int row = r0 + i * 32;                                                  \
            float4 v = ra[i];                                                             \
            if (is_iou) { v.x += ra2[i].x; v.y += ra2[i].y; v.z += ra2[i].z; v.w += ra2[i].w; } \
            *(float4*)&(As)[row * SROW + kq] = v;                                         \
        }                                                                                 \
    } while (0)

    // prologue: chunk 0
    LG_LOAD_A(0);
    LG_CPASYNC_B(0, smem + 128 * SROW);
    asm volatile("cp.async.commit_group;" ::: "memory");
    LG_STORE_A(smem);
    asm volatile("cp.async.wait_group 0;" ::: "memory");
    __syncthreads();

    for (int ci = 0; ci < 8; ci++) {
        float* bufn = smem + (size_t)((ci + 1) & 1) * STAGE_FLOATS;
        if (ci + 1 < 8) {
            LG_LOAD_A(ci + 1);
            LG_CPASYNC_B(ci + 1, bufn + 128 * SROW);
            asm volatile("cp.async.commit_group;" ::: "memory");
        }
        const float* As = smem + (size_t)(ci & 1) * STAGE_FLOATS;
        const float* Bs = As + 128 * SROW;
        MMA_COMPUTE(As, Bs);
        __syncthreads();
        if (ci + 1 < 8) {
            LG_STORE_A(bufn);
            asm volatile("cp.async.wait_group 0;" ::: "memory");
            __syncthreads();
        }
    }

#pragma unroll
    for (int mt = 0; mt < 2; mt++) {
        const int row = bm + wm * 32 + mt * 16 + g;
#pragma unroll
        for (int nt = 0; nt < 8; nt++) {
            const int col = tn * 128 + wn * 64 + nt * 8 + 2 * c4;
            if (row < Mrows)
                *(float2*)&C[(size_t)row * ldc + col] = make_float2(acc[mt][nt][0], acc[mt][nt][1]);
            if (row + 8 < Mrows)
                *(float2*)&C[(size_t)(row + 8) * ldc + col] = make_float2(acc[mt][nt][2], acc[mt][nt][3]);
        }
    }
#undef LG_LOAD_A
#undef LG_CPASYNC_B
#undef LG_STORE_A
}

// ============================ epilogues (float4, 4 nodes / block) ============================
__device__ __forceinline__ float sigmoidf_(float x) { return __fdividef(1.f, 1.f + __expf(-x)); }
__device__ __forceinline__ float ftanh_(float x) {
    float t = __expf(2.f * x);
    return 1.f - __fdividef(2.f, t + 1.f);
}
__device__ __forceinline__ float4 f4add(float4 a, float4 b) {
    return make_float4(a.x + b.x, a.y + b.y, a.z + b.z, a.w + b.w);
}

__global__ void leaf_epi(float* __restrict__ c, float* __restrict__ h) {
    const int j = threadIdx.x >> 6;                  // node within block
    const int q = (threadIdx.x & 63) * 4;            // col4
    const int n = LEAF_START + blockIdx.x * 4 + j;   // 32768 leaves, grid 8192
    const float* pre = g_PRE + (size_t)n * 1024;
    float4 pi = f4add(*(const float4*)&pre[q],        *(const float4*)&g_BIO[q]);
    float4 po = f4add(*(const float4*)&pre[256 + q],  *(const float4*)&g_BIO[256 + q]);
    float4 pu = f4add(*(const float4*)&pre[512 + q],  *(const float4*)&g_BIO[512 + q]);
    float4 cn, hn;
    {
        float cv, hv;
#define GATE(X) do { \
        float iv = sigmoidf_(pi.X), ov = sigmoidf_(po.X), uv = ftanh_(pu.X); \
        cv = iv * uv; hv = ov * ftanh_(cv); cn.X = cv; hn.X = hv; } while (0)
        GATE(x); GATE(y); GATE(z); GATE(w);
#undef GATE
    }
    *(float4*)&c[(size_t)n * NMEM + q] = cn;
    *(float4*)&h[(size_t)n * NMEM + q] = hn;
}

__global__ void level_epi(float* __restrict__ c, float* __restrict__ h,
                          int start, int sc, int S) {
    const int j = threadIdx.x >> 6;
    const int q = (threadIdx.x & 63) * 4;
    const int r = blockIdx.x * 4 + j;
    if (r >= S) return;
    const int n = start + r;
    const float* pre = g_PRE + (size_t)n * 1024;
    const float* piou = g_PIOU + (size_t)r * 768;
    float4 pi = f4add(f4add(*(const float4*)&piou[q],       *(const float4*)&pre[q]),       *(const float4*)&g_BIO[q]);
    float4 po = f4add(f4add(*(const float4*)&piou[256 + q], *(const float4*)&pre[256 + q]), *(const float4*)&g_BIO[256 + q]);
    float4 pu = f4add(f4add(*(const float4*)&piou[512 + q], *(const float4*)&pre[512 + q]), *(const float4*)&g_BIO[512 + q]);
    float4 fx = f4add(*(const float4*)&pre[768 + q], *(const float4*)&g_BF[q]);
    float4 pfl = f4add(*(const float4*)&g_PF[(size_t)(2 * r) * 256 + q], fx);
    float4 pfr = f4add(*(const float4*)&g_PF[(size_t)(2 * r + 1) * 256 + q], fx);
    float4 cl = *(const float4*)&c[(size_t)(sc + 2 * r) * NMEM + q];
    float4 cr = *(const float4*)&c[(size_t)(sc + 2 * r + 1) * NMEM + q];
    float4 cn, hn;
    {
#define GATE(X) do { \
        float iv = sigmoidf_(pi.X), ov = sigmoidf_(po.X), uv = ftanh_(pu.X); \
        float fl = sigmoidf_(pfl.X), fr = sigmoidf_(pfr.X); \
        float cv = iv * uv + fl * cl.X + fr * cr.X; \
        cn.X = cv; hn.X = ov * ftanh_(cv); } while (0)
        GATE(x); GATE(y); GATE(z); GATE(w);
#undef GATE
    }
    *(float4*)&c[(size_t)n * NMEM + q] = cn;
    *(float4*)&h[(size_t)n * NMEM + q] = hn;
}

// ============================ launcher ============================
extern "C" void kernel_launch(void* const* d_in, const int* in_sizes, int n_in,
                              void* d_out, int out_size) {
    const float* inputs = (const float*)d_in[0];
    const float* W_ioux = (const float*)d_in[1];
    const float* b_ioux = (const float*)d_in[2];
    const float* W_iouh = (const float*)d_in[3];
    const float* b_iouh = (const float*)d_in[4];
    const float* W_fx   = (const float*)d_in[5];
    const float* b_fx   = (const float*)d_in[6];
    const float* W_fh   = (const float*)d_in[7];
    const float* b_fh   = (const float*)d_in[8];
    (void)in_sizes; (void)n_in; (void)out_size;

    float* c = (float*)d_out;                   // out[0] = c  [N,256]
    float* h = c + (size_t)NN * NMEM;           // out[1] = h  [N,256]

    float *pPRE, *pPIOU, *pPF, *pW1, *pWIOU, *pWF;
    cudaGetSymbolAddress((void**)&pPRE,  g_PRE);
    cudaGetSymbolAddress((void**)&pPIOU, g_PIOU);
    cudaGetSymbolAddress((void**)&pPF,   g_PF);
    cudaGetSymbolAddress((void**)&pW1,   g_W1);
    cudaGetSymbolAddress((void**)&pWIOU, g_WIOU);
    cudaGetSymbolAddress((void**)&pWF,   g_WF);

    const int SMEM_BYTES = 2 * STAGE_FLOATS * 4;   // 73728 bytes
    cudaFuncSetAttribute(gemm_mma,   cudaFuncAttributeMaxDynamicSharedMemorySize, SMEM_BYTES);
    cudaFuncSetAttribute(level_gemm, cudaFuncAttributeMaxDynamicSharedMemorySize, SMEM_BYTES);

    build_w1<<<(1024 * 320 + 255) / 256, 256>>>(W_ioux, W_fx);
    build_misc<<<(263168 + 255) / 256, 256>>>(W_iouh, W_fh, b_ioux, b_iouh, b_fx, b_fh);

    // gemm1: PRE = inputs @ [W_ioux|W_fx]^T  (M=65535, K=300 pad 320, N=1024)
    {
        dim3 grd(8, 512);        // x = column tiles (fast), y = row tiles
        gemm_mma<<<grd, 256, SMEM_BYTES>>>(inputs, NN, 300, 1200, pW1, 320, pPRE, 1024, 10);
    }

    // leaves (depth 15): 32768 nodes, 4/block
    leaf_epi<<<8192, 256>>>(c, h);

    // internal levels bottom-up
    for (int d = 14; d >= 0; --d) {
        const int S = 1 << d;
        const int start = S - 1;
        const int sc = 2 * S - 1;
        const float* A = h + (size_t)sc * NMEM;        // children rows [2S,256]
        const int tiles_m_iou = (S + 127) / 128;
        const int tiles_m_f   = (2 * S + 127) / 128;
        const int gx = tiles_m_iou * 6 + tiles_m_f * 2;
        level_gemm<<<gx, 256, SMEM_BYTES>>>(A, S, pWIOU, pWF, pPIOU, pPF, tiles_m_iou);
        level_epi<<<(S + 3) / 4, 256>>>(c, h, start, sc, S);
    }
}

// round 6
// speedup vs baseline: 4.1566x; 1.0196x over previous
#include <cuda_runtime.h>
#include <math.h>
#include <cstdint>

#define NN 65535            // total nodes
#define LEAF_START 32767
#define NMEM 256

// ---- scratch (device globals; no allocation allowed) ----
__device__ float g_PRE[(size_t)NN * 1024];      // [N,1024]: 0..767 x@W_ioux^T, 768..1023 x@W_fx^T
__device__ float g_PIOU[(size_t)16384 * 768];   // per-level iou recurrent term [S,768]
__device__ float g_PF[(size_t)32768 * 256];     // per-level child f-projections [2S,256]
__device__ float g_W1[1024 * 320];              // gemm1 B: [n=1024][k=320] tf32-rounded, K padded
__device__ float g_WIOU[768 * 256];             // W_iouh tf32-rounded [n][k]
__device__ float g_WF[256 * 256];               // W_fh tf32-rounded [n][k]
__device__ float g_BIO[768];                    // b_ioux + b_iouh
__device__ float g_BF[256];                     // b_fx + b_fh

// ============================ helpers ============================
__device__ __forceinline__ uint32_t smem_u32(const void* p) {
    uint32_t a;
    asm("{ .reg .u64 t; cvta.to.shared.u64 t, %1; cvt.u32.u64 %0, t; }" : "=r"(a) : "l"(p));
    return a;
}
__device__ __forceinline__ float tf32_rna(float v) {
    uint32_t t;
    asm("cvt.rna.tf32.f32 %0, %1;" : "=r"(t) : "f"(v));
    return __uint_as_float(t);
}
__device__ __forceinline__ uint32_t tf32_rna_u(float v) {
    uint32_t t;
    asm("cvt.rna.tf32.f32 %0, %1;" : "=r"(t) : "f"(v));
    return t;
}

// ============================ weight repacking ============================
__global__ void build_w1(const float* __restrict__ W_ioux, const float* __restrict__ W_fx) {
    int idx = blockIdx.x * blockDim.x + threadIdx.x;
    if (idx >= 1024 * 320) return;
    int j = idx / 320, k = idx - j * 320;
    float v = 0.f;
    if (k < 300) v = (j < 768) ? W_ioux[j * 300 + k] : W_fx[(j - 768) * 300 + k];
    g_W1[idx] = tf32_rna(v);
}

__global__ void build_misc(const float* __restrict__ W_iouh, const float* __restrict__ W_fh,
                           const float* __restrict__ b_ioux, const float* __restrict__ b_iouh,
                           const float* __restrict__ b_fx, const float* __restrict__ b_fh) {
    int i = blockIdx.x * blockDim.x + threadIdx.x;
    if (i < 196608)       g_WIOU[i] = tf32_rna(W_iouh[i]);
    else if (i < 262144)  g_WF[i - 196608] = tf32_rna(W_fh[i - 196608]);
    else if (i < 262912)  { int j = i - 262144; g_BIO[j] = b_ioux[j] + b_iouh[j]; }
    else if (i < 263168)  { int j = i - 262912; g_BF[j]  = b_fx[j]  + b_fh[j];  }
}

// ============================ smem tiling constants ============================
#define SROW 36                        // 32 + 4 pad floats per smem row
#define TILE_FLOATS (128 * SROW)       // one 128x32 tile
#define STAGE_FLOATS (2 * TILE_FLOATS) // A tile + B tile per stage

// ============================ gemm1: 4 warps, 64x64 warp tile, 3-stage ============================
__device__ __forceinline__ void load_stage1(float* As, float* Bs,
                                            const float* __restrict__ A, int M, int lda, int avalid_bytes,
                                            const float* __restrict__ B, int ldb,
                                            int bm, int bn, int k0, int tid) {
    const int r0 = tid >> 3;          // 0..15
    const int kq = (tid & 7) * 4;     // 0..28
#pragma unroll
    for (int i = 0; i < 8; i++) {
        const int row = r0 + i * 16;
        {
            const bool ok = (bm + row < M) && ((k0 + kq) * 4 < avalid_bytes);
            const float* ga = ok ? (A + (size_t)(bm + row) * lda + k0 + kq) : A;
            uint32_t sa = smem_u32(As + row * SROW + kq);
            uint32_t sz = ok ? 16u : 0u;
            asm volatile("cp.async.cg.shared.global [%0], [%1], 16, %2;"
                         :: "r"(sa), "l"(ga), "r"(sz) : "memory");
        }
        {
            const float* gb = B + (size_t)(bn + row) * ldb + k0 + kq;
            uint32_t sb = smem_u32(Bs + row * SROW + kq);
            asm volatile("cp.async.cg.shared.global [%0], [%1], 16;"
                         :: "r"(sb), "l"(gb) : "memory");
        }
    }
}

// 64x64 warp-tile compute: 4 mt x 8 nt, 1:1 LDS:MMA
#define MMA_COMPUTE4(As, Bs)                                                           \
    do {                                                                               \
        _Pragma("unroll")                                                              \
        for (int kt = 0; kt < 4; kt++) {                                               \
            const int kk = kt * 8 + c4;                                                \
            uint32_t a[4][4];                                                          \
            _Pragma("unroll")                                                          \
            for (int mt = 0; mt < 4; mt++) {                                           \
                const int row = wm * 64 + mt * 16 + g;                                 \
                a[mt][0] = tf32_rna_u((As)[row * SROW + kk]);                          \
                a[mt][1] = tf32_rna_u((As)[(row + 8) * SROW + kk]);                    \
                a[mt][2] = tf32_rna_u((As)[row * SROW + kk + 4]);                      \
                a[mt][3] = tf32_rna_u((As)[(row + 8) * SROW + kk + 4]);                \
            }                                                                          \
            uint32_t b[8][2];                                                          \
            _Pragma("unroll")                                                          \
            for (int nt = 0; nt < 8; nt++) {                                           \
                const int nrow = wn * 64 + nt * 8 + g;                                 \
                b[nt][0] = __float_as_uint((Bs)[nrow * SROW + kk]);                    \
                b[nt][1] = __float_as_uint((Bs)[nrow * SROW + kk + 4]);                \
            }                                                                          \
            _Pragma("unroll")                                                          \
            for (int mt = 0; mt < 4; mt++)                                             \
                _Pragma("unroll")                                                      \
                for (int nt = 0; nt < 8; nt++) {                                       \
                    asm volatile(                                                      \
                        "mma.sync.aligned.m16n8k8.row.col.f32.tf32.tf32.f32 "          \
                        "{%0,%1,%2,%3}, {%4,%5,%6,%7}, {%8,%9}, {%0,%1,%2,%3};"        \
                        : "+f"(acc[mt][nt][0]), "+f"(acc[mt][nt][1]),                  \
                          "+f"(acc[mt][nt][2]), "+f"(acc[mt][nt][3])                   \
                        : "r"(a[mt][0]), "r"(a[mt][1]), "r"(a[mt][2]), "r"(a[mt][3]),  \
                          "r"(b[nt][0]), "r"(b[nt][1]));                               \
                }                                                                      \
        }                                                                              \
    } while (0)

__global__ __launch_bounds__(128)
void gemm_mma(const float* __restrict__ A, int M, int lda, int avalid_bytes,
              const float* __restrict__ B, int ldb,
              float* __restrict__ C, int ldc, int KC) {
    extern __shared__ float smem[];

    const int tid  = threadIdx.x;
    const int wid  = tid >> 5;
    const int lane = tid & 31;
    const int wm = wid & 1, wn = wid >> 1;     // 2x2 warp grid, 64x64 warp tiles
    const int g  = lane >> 2, c4 = lane & 3;
    // column-major CTA order: all column tiles of a row-block run consecutively (A stays L2-hot)
    const int bm = blockIdx.y * 128;
    const int bn = blockIdx.x * 128;

    float acc[4][8][4];
#pragma unroll
    for (int mt = 0; mt < 4; mt++)
#pragma unroll
        for (int nt = 0; nt < 8; nt++)
#pragma unroll
            for (int i = 0; i < 4; i++) acc[mt][nt][i] = 0.f;

    // prologue: stages 0, 1
    load_stage1(smem, smem + TILE_FLOATS, A, M, lda, avalid_bytes, B, ldb, bm, bn, 0, tid);
    asm volatile("cp.async.commit_group;" ::: "memory");
    load_stage1(smem + STAGE_FLOATS, smem + STAGE_FLOATS + TILE_FLOATS,
                A, M, lda, avalid_bytes, B, ldb, bm, bn, 32, tid);
    asm volatile("cp.async.commit_group;" ::: "memory");
    asm volatile("cp.async.wait_group 1;" ::: "memory");
    __syncthreads();

    int sc_ = 0;   // stage index of current chunk
    for (int ci = 0; ci < KC; ci++) {
        const float* As = smem + (size_t)sc_ * STAGE_FLOATS;
        const float* Bs = As + TILE_FLOATS;
        MMA_COMPUTE4(As, Bs);
        if (ci + 2 < KC) {
            int sn = sc_ + 2; if (sn >= 3) sn -= 3;
            float* Ad = smem + (size_t)sn * STAGE_FLOATS;
            load_stage1(Ad, Ad + TILE_FLOATS, A, M, lda, avalid_bytes, B, ldb, bm, bn, (ci + 2) * 32, tid);
            asm volatile("cp.async.commit_group;" ::: "memory");
            asm volatile("cp.async.wait_group 1;" ::: "memory");
        } else {
            asm volatile("cp.async.wait_group 0;" ::: "memory");
        }
        __syncthreads();
        if (++sc_ == 3) sc_ = 0;
    }

#pragma unroll
    for (int mt = 0; mt < 4; mt++) {
        const int row = bm + wm * 64 + mt * 16 + g;
#pragma unroll
        for (int nt = 0; nt < 8; nt++) {
            const int col = bn + wn * 64 + nt * 8 + 2 * c4;
            if (row < M)
                *(float2*)&C[(size_t)row * ldc + col] = make_float2(acc[mt][nt][0], acc[mt][nt][1]);
            if (row + 8 < M)
                *(float2*)&C[(size_t)(row + 8) * ldc + col] = make_float2(acc[mt][nt][2], acc[mt][nt][3]);
        }
    }
}

// ============================ merged per-level GEMM (8 warps, 32x64 warp tile) ============================
#define MMA_COMPUTE(As, Bs)                                                            \
    do {                                                                               \
        _Pragma("unroll")                                                              \
        for (int kt = 0; kt < 4; kt++) {                                               \
            const int kk = kt * 8 + c4;                                                \
            uint32_t a[2][4];                                                          \
            _Pragma("unroll")                                                          \
            for (int mt = 0; mt < 2; mt++) {                                           \
                const int row = wm * 32 + mt * 16 + g;                                 \
                a[mt][0] = tf32_rna_u((As)[row * SROW + kk]);                          \
                a[mt][1] = tf32_rna_u((As)[(row + 8) * SROW + kk]);                    \
                a[mt][2] = tf32_rna_u((As)[row * SROW + kk + 4]);                      \
                a[mt][3] = tf32_rna_u((As)[(row + 8) * SROW + kk + 4]);                \
            }                                                                          \
            uint32_t b[8][2];                                                          \
            _Pragma("unroll")                                                          \
            for (int nt = 0; nt < 8; nt++) {                                           \
                const int nrow = wn * 64 + nt * 8 + g;                                 \
                b[nt][0] = __float_as_uint((Bs)[nrow * SROW + kk]);                    \
                b[nt][1] = __float_as_uint((Bs)[nrow * SROW + kk + 4]);                \
            }                                                                          \
            _Pragma("unroll")                                                          \
            for (int mt = 0; mt < 2; mt++)                                             \
                _Pragma("unroll")                                                      \
                for (int nt = 0; nt < 8; nt++) {                                       \
                    asm volatile(                                                      \
                        "mma.sync.aligned.m16n8k8.row.col.f32.tf32.tf32.f32 "          \
                        "{%0,%1,%2,%3}, {%4,%5,%6,%7}, {%8,%9}, {%0,%1,%2,%3};"        \
                        : "+f"(acc[mt][nt][0]), "+f"(acc[mt][nt][1]),                  \
                          "+f"(acc[mt][nt][2]), "+f"(acc[mt][nt][3])                   \
                        : "r"(a[mt][0]), "r"(a[mt][1]), "r"(a[mt][2]), "r"(a[mt][3]),  \
                          "r"(b[nt][0]), "r"(b[nt][1]));                               \
                }                                                                      \
        }                                                                              \
    } while (0)

__global__ __launch_bounds__(256)
void level_gemm(const float* __restrict__ hbase, int S,
                const float* __restrict__ WIOU, const float* __restrict__ WF,
                float* __restrict__ PIOU, float* __restrict__ PF, int tiles_m_iou) {
    extern __shared__ float smem[];

    const int tid  = threadIdx.x;
    const int wid  = tid >> 5;
    const int lane = tid & 31;
    const int wm = wid & 3, wn = wid >> 2;
    const int g  = lane >> 2, c4 = lane & 3;

    int t = blockIdx.x;
    const bool is_iou = (t < tiles_m_iou * 6);
    int tm, tn, Mrows, ldc;
    const float* Bsrc;
    float* C;
    if (is_iou) { tm = t / 6; tn = t - tm * 6; Mrows = S;     Bsrc = WIOU + (size_t)tn * 128 * 256; C = PIOU; ldc = 768; }
    else { int t2 = t - tiles_m_iou * 6; tm = t2 >> 1; tn = t2 & 1; Mrows = 2 * S; Bsrc = WF + (size_t)tn * 128 * 256; C = PF; ldc = 256; }
    const int bm = tm * 128;

    const int r0 = tid >> 3;          // 0..31
    const int kq = (tid & 7) * 4;     // 0..28

    float acc[2][8][4];
#pragma unroll
    for (int mt = 0; mt < 2; mt++)
#pragma unroll
        for (int nt = 0; nt < 8; nt++)
#pragma unroll
            for (int i = 0; i < 4; i++) acc[mt][nt][i] = 0.f;

    float4 ra[4], ra2[4];
    const float4 z4 = make_float4(0.f, 0.f, 0.f, 0.f);

#define LG_LOAD_A(ci)                                                                     \
    do {                                                                                  \
        const int k0 = (ci) * 32;                                                         \
        _Pragma("unroll")                                                                 \
        for (int i = 0; i < 4; i++) {                                                     \
            const int m = bm + r0 + i * 32;                                               \
            if (is_iou) {                                                                 \
                if (m < S) {                                                              \
                    ra[i]  = *(const float4*)&hbase[(size_t)(2 * m) * 256 + k0 + kq];     \
                    ra2[i] = *(const float4*)&hbase[(size_t)(2 * m + 1) * 256 + k0 + kq]; \
                } else { ra[i] = z4; ra2[i] = z4; }                                       \
            } else {                                                                      \
                ra[i] = (m < Mrows) ? *(const float4*)&hbase[(size_t)m * 256 + k0 + kq]   \
                                    : z4;                                                 \
            }                                                                             \
        }                                                                                 \
    } while (0)

#define LG_CPASYNC_B(ci, Bs)                                                              \
    do {                                                                                  \
        const int k0 = (ci) * 32;                                                         \
        _Pragma("unroll")                                                                 \
        for (int i = 0; i < 4; i++) {                                                     \
            const int row = r0 + i * 32;                                                  \
            const float* gb = Bsrc + (size_t)row * 256 + k0 + kq;                         \
            uint32_t sb = smem_u32((Bs) + row * SROW + kq);                               \
            asm volatile("cp.async.cg.shared.global [%0], [%1], 16;"                      \
                         :: "r"(sb), "l"(gb) : "memory");                                 \
        }                                                                                 \
    } while (0)

#define LG_STORE_A(As)                                                                    \
    do {                                                                                  \
        _Pragma("unroll")                                                                 \
        for (int i = 0; i < 4; i++) {                                                     \
            const int row = r0 + i * 32;                                                  \
            float4 v = ra[i];                                                             \
            if (is_iou) { v.x += ra2[i].x; v.y += ra2[i].y; v.z += ra2[i].z; v.w += ra2[i].w; } \
            *(float4*)&(As)[row * SROW + kq] = v;                                         \
        }                                                                                 \
    } while (0)

    // prologue: chunk 0
    LG_LOAD_A(0);
    LG_CPASYNC_B(0, smem + TILE_FLOATS);
    asm volatile("cp.async.commit_group;" ::: "memory");
    LG_STORE_A(smem);
    asm volatile("cp.async.wait_group 0;" ::: "memory");
    __syncthreads();

    for (int ci = 0; ci < 8; ci++) {
        float* bufn = smem + (size_t)((ci + 1) & 1) * STAGE_FLOATS;
        if (ci + 1 < 8) {
            LG_LOAD_A(ci + 1);
            LG_CPASYNC_B(ci + 1, bufn + TILE_FLOATS);
            asm volatile("cp.async.commit_group;" ::: "memory");
        }
        const float* As = smem + (size_t)(ci & 1) * STAGE_FLOATS;
        const float* Bs = As + TILE_FLOATS;
        MMA_COMPUTE(As, Bs);
        __syncthreads();
        if (ci + 1 < 8) {
            LG_STORE_A(bufn);
            asm volatile("cp.async.wait_group 0;" ::: "memory");
            __syncthreads();
        }
    }

#pragma unroll
    for (int mt = 0; mt < 2; mt++) {
        const int row = bm + wm * 32 + mt * 16 + g;
#pragma unroll
        for (int nt = 0; nt < 8; nt++) {
            const int col = tn * 128 + wn * 64 + nt * 8 + 2 * c4;
            if (row < Mrows)
                *(float2*)&C[(size_t)row * ldc + col] = make_float2(acc[mt][nt][0], acc[mt][nt][1]);
            if (row + 8 < Mrows)
                *(float2*)&C[(size_t)(row + 8) * ldc + col] = make_float2(acc[mt][nt][2], acc[mt][nt][3]);
        }
    }
#undef LG_LOAD_A
#undef LG_CPASYNC_B
#undef LG_STORE_A
}

// ============================ epilogues (float4, 4 nodes / block) ============================
__device__ __forceinline__ float sigmoidf_(float x) { return __fdividef(1.f, 1.f + __expf(-x)); }
__device__ __forceinline__ float ftanh_(float x) {
    float t = __expf(2.f * x);
    return 1.f - __fdividef(2.f, t + 1.f);
}
__device__ __forceinline__ float4 f4add(float4 a, float4 b) {
    return make_float4(a.x + b.x, a.y + b.y, a.z + b.z, a.w + b.w);
}

__global__ void leaf_epi(float* __restrict__ c, float* __restrict__ h) {
    const int j = threadIdx.x >> 6;                  // node within block
    const int q = (threadIdx.x & 63) * 4;            // col4
    const int n = LEAF_START + blockIdx.x * 4 + j;   // 32768 leaves, grid 8192
    const float* pre = g_PRE + (size_t)n * 1024;
    float4 pi = f4add(*(const float4*)&pre[q],        *(const float4*)&g_BIO[q]);
    float4 po = f4add(*(const float4*)&pre[256 + q],  *(const float4*)&g_BIO[256 + q]);
    float4 pu = f4add(*(const float4*)&pre[512 + q],  *(const float4*)&g_BIO[512 + q]);
    float4 cn, hn;
    {
        float cv, hv;
#define GATE(X) do { \
        float iv = sigmoidf_(pi.X), ov = sigmoidf_(po.X), uv = ftanh_(pu.X); \
        cv = iv * uv; hv = ov * ftanh_(cv); cn.X = cv; hn.X = hv; } while (0)
        GATE(x); GATE(y); GATE(z); GATE(w);
#undef GATE
    }
    *(float4*)&c[(size_t)n * NMEM + q] = cn;
    *(float4*)&h[(size_t)n * NMEM + q] = hn;
}

__global__ void level_epi(float* __restrict__ c, float* __restrict__ h,
                          int start, int sc, int S) {
    const int j = threadIdx.x >> 6;
    const int q = (threadIdx.x & 63) * 4;
    const int r = blockIdx.x * 4 + j;
    if (r >= S) return;
    const int n = start + r;
    const float* pre = g_PRE + (size_t)n * 1024;
    const float* piou = g_PIOU + (size_t)r * 768;
    float4 pi = f4add(f4add(*(const float4*)&piou[q],       *(const float4*)&pre[q]),       *(const float4*)&g_BIO[q]);
    float4 po = f4add(f4add(*(const float4*)&piou[256 + q], *(const float4*)&pre[256 + q]), *(const float4*)&g_BIO[256 + q]);
    float4 pu = f4add(f4add(*(const float4*)&piou[512 + q], *(const float4*)&pre[512 + q]), *(const float4*)&g_BIO[512 + q]);
    float4 fx = f4add(*(const float4*)&pre[768 + q], *(const float4*)&g_BF[q]);
    float4 pfl = f4add(*(const float4*)&g_PF[(size_t)(2 * r) * 256 + q], fx);
    float4 pfr = f4add(*(const float4*)&g_PF[(size_t)(2 * r + 1) * 256 + q], fx);
    float4 cl = *(const float4*)&c[(size_t)(sc + 2 * r) * NMEM + q];
    float4 cr = *(const float4*)&c[(size_t)(sc + 2 * r + 1) * NMEM + q];
    float4 cn, hn;
    {
#define GATE(X) do { \
        float iv = sigmoidf_(pi.X), ov = sigmoidf_(po.X), uv = ftanh_(pu.X); \
        float fl = sigmoidf_(pfl.X), fr = sigmoidf_(pfr.X); \
        float cv = iv * uv + fl * cl.X + fr * cr.X; \
        cn.X = cv; hn.X = ov * ftanh_(cv); } while (0)
        GATE(x); GATE(y); GATE(z); GATE(w);
#undef GATE
    }
    *(float4*)&c[(size_t)n * NMEM + q] = cn;
    *(float4*)&h[(size_t)n * NMEM + q] = hn;
}

// ============================ launcher ============================
extern "C" void kernel_launch(void* const* d_in, const int* in_sizes, int n_in,
                              void* d_out, int out_size) {
    const float* inputs = (const float*)d_in[0];
    const float* W_ioux = (const float*)d_in[1];
    const float* b_ioux = (const float*)d_in[2];
    const float* W_iouh = (const float*)d_in[3];
    const float* b_iouh = (const float*)d_in[4];
    const float* W_fx   = (const float*)d_in[5];
    const float* b_fx   = (const float*)d_in[6];
    const float* W_fh   = (const float*)d_in[7];
    const float* b_fh   = (const float*)d_in[8];
    (void)in_sizes; (void)n_in; (void)out_size;

    float* c = (float*)d_out;                   // out[0] = c  [N,256]
    float* h = c + (size_t)NN * NMEM;           // out[1] = h  [N,256]

    float *pPRE, *pPIOU, *pPF, *pW1, *pWIOU, *pWF;
    cudaGetSymbolAddress((void**)&pPRE,  g_PRE);
    cudaGetSymbolAddress((void**)&pPIOU, g_PIOU);
    cudaGetSymbolAddress((void**)&pPF,   g_PF);
    cudaGetSymbolAddress((void**)&pW1,   g_W1);
    cudaGetSymbolAddress((void**)&pWIOU, g_WIOU);
    cudaGetSymbolAddress((void**)&pWF,   g_WF);

    const int SMEM1 = 3 * STAGE_FLOATS * 4;    // 110592 bytes (3-stage)
    const int SMEML = 2 * STAGE_FLOATS * 4;    // 73728 bytes (2-stage)
    cudaFuncSetAttribute(gemm_mma,   cudaFuncAttributeMaxDynamicSharedMemorySize, SMEM1);
    cudaFuncSetAttribute(level_gemm, cudaFuncAttributeMaxDynamicSharedMemorySize, SMEML);

    build_w1<<<(1024 * 320 + 255) / 256, 256>>>(W_ioux, W_fx);
    build_misc<<<(263168 + 255) / 256, 256>>>(W_iouh, W_fh, b_ioux, b_iouh, b_fx, b_fh);

    // gemm1: PRE = inputs @ [W_ioux|W_fx]^T  (M=65535, K=300 pad 320, N=1024)
    {
        dim3 grd(8, 512);        // x = column tiles (fast), y = row tiles
        gemm_mma<<<grd, 128, SMEM1>>>(inputs, NN, 300, 1200, pW1, 320, pPRE, 1024, 10);
    }

    // leaves (depth 15): 32768 nodes, 4/block
    leaf_epi<<<8192, 256>>>(c, h);

    // internal levels bottom-up
    for (int d = 14; d >= 0; --d) {
        const int S = 1 << d;
        const int start = S - 1;
        const int sc = 2 * S - 1;
        const float* A = h + (size_t)sc * NMEM;        // children rows [2S,256]
        const int tiles_m_iou = (S + 127) / 128;
        const int tiles_m_f   = (2 * S + 127) / 128;
        const int gx = tiles_m_iou * 6 + tiles_m_f * 2;
        level_gemm<<<gx, 256, SMEML>>>(A, S, pWIOU, pWF, pPIOU, pPF, tiles_m_iou);
        level_epi<<<(S + 3) / 4, 256>>>(c, h, start, sc, S);
    }
}

// round 7
// speedup vs baseline: 4.7482x; 1.1423x over previous
#include <cuda_runtime.h>
#include <cuda_fp16.h>
#include <math.h>
#include <cstdint>

#define NN 65535            // total nodes
#define LEAF_START 32767
#define NMEM 256

// ---- scratch (device globals; no allocation allowed) ----
__device__ float  g_PRE[(size_t)NN * 1024];      // [N,1024]: 0..767 x@W_ioux^T, 768..1023 x@W_fx^T
__device__ float  g_PIOU[(size_t)16384 * 768];   // per-level iou recurrent term [S,768]
__device__ float  g_PF[(size_t)32768 * 256];     // per-level child f-projections [2S,256]
__device__ __half g_X16[(size_t)NN * 320];       // inputs fp16, K padded 300->320
__device__ __half g_W1h[1024 * 320];             // gemm1 B fp16 [n][k]
__device__ __half g_WIOUh[768 * 256];            // W_iouh fp16 [n][k]
__device__ __half g_WFh[256 * 256];              // W_fh fp16 [n][k]
__device__ __half g_H16[(size_t)NN * 256];       // h in fp16
__device__ float  g_BIO[768];                    // b_ioux + b_iouh
__device__ float  g_BF[256];                     // b_fx + b_fh

// ============================ helpers ============================
__device__ __forceinline__ uint32_t smem_u32(const void* p) {
    uint32_t a;
    asm("{ .reg .u64 t; cvta.to.shared.u64 t, %1; cvt.u32.u64 %0, t; }" : "=r"(a) : "l"(p));
    return a;
}
__device__ __forceinline__ uint32_t hadd2u(uint32_t a, uint32_t b) {
    __half2 r = __hadd2(*reinterpret_cast<__half2*>(&a), *reinterpret_cast<__half2*>(&b));
    return *reinterpret_cast<uint32_t*>(&r);
}

// ============================ conversion / repacking ============================
__global__ void conv_x(const float* __restrict__ inputs) {
    int idx = blockIdx.x * blockDim.x + threadIdx.x;     // over 65535*160 half2
    if (idx >= NN * 160) return;
    int row = idx / 160, c2 = idx - row * 160;
    int k = 2 * c2;
    __half2 v;
    if (k < 300) {
        float2 f = *(const float2*)&inputs[(size_t)row * 300 + k];
        v = __floats2half2_rn(f.x, f.y);
    } else {
        v = __floats2half2_rn(0.f, 0.f);
    }
    *(__half2*)&g_X16[(size_t)row * 320 + k] = v;
}

__global__ void build_w1h(const float* __restrict__ W_ioux, const float* __restrict__ W_fx) {
    int idx = blockIdx.x * blockDim.x + threadIdx.x;
    if (idx >= 1024 * 320) return;
    int j = idx / 320, k = idx - j * 320;
    float v = 0.f;
    if (k < 300) v = (j < 768) ? W_ioux[j * 300 + k] : W_fx[(j - 768) * 300 + k];
    g_W1h[idx] = __float2half_rn(v);
}

__global__ void build_misch(const float* __restrict__ W_iouh, const float* __restrict__ W_fh,
                            const float* __restrict__ b_ioux, const float* __restrict__ b_iouh,
                            const float* __restrict__ b_fx, const float* __restrict__ b_fh) {
    int i = blockIdx.x * blockDim.x + threadIdx.x;
    if (i < 196608)       g_WIOUh[i] = __float2half_rn(W_iouh[i]);
    else if (i < 262144)  g_WFh[i - 196608] = __float2half_rn(W_fh[i - 196608]);
    else if (i < 262912)  { int j = i - 262144; g_BIO[j] = b_ioux[j] + b_iouh[j]; }
    else if (i < 263168)  { int j = i - 262912; g_BF[j]  = b_fx[j]  + b_fh[j];  }
}

// ============================ smem tiling constants (fp16) ============================
#define SROW_H 40                       // 32 + 8 pad halves per smem row (80 B, conflict-free)
#define TILE_H (128 * SROW_H)           // one 128x32-half tile
#define STAGE_H (2 * TILE_H)            // A + B per stage

// fp16 mma: D += A(16x16) * B^T(8x16)
#define HMMA(accp, a0, a1, a2, a3, b0, b1)                                         \
    asm volatile(                                                                  \
        "mma.sync.aligned.m16n8k16.row.col.f32.f16.f16.f32 "                       \
        "{%0,%1,%2,%3}, {%4,%5,%6,%7}, {%8,%9}, {%0,%1,%2,%3};"                    \
        : "+f"((accp)[0]), "+f"((accp)[1]), "+f"((accp)[2]), "+f"((accp)[3])       \
        : "r"(a0), "r"(a1), "r"(a2), "r"(a3), "r"(b0), "r"(b1))

// ============================ gemm1: X16[M,320] @ W1h[1024,320]^T -> PRE fp32 ============================
// 128 threads, 2x2 warps, 64x64 warp tiles, 3-stage cp.async.
__device__ __forceinline__ void g1_load(__half* dst, const __half* __restrict__ X,
                                        const __half* __restrict__ W,
                                        int bm, int bn, int k0, int tid) {
    const int r0 = tid >> 2;          // 0..31
    const int cq = (tid & 3) * 8;     // half offset: 0,8,16,24 (16B chunks)
#pragma unroll
    for (int i = 0; i < 4; i++) {
        const int row = r0 + i * 32;
        {
            const bool ok = (bm + row) < NN;
            const __half* ga = ok ? (X + (size_t)(bm + row) * 320 + k0 + cq) : X;
            uint32_t sa = smem_u32(dst + row * SROW_H + cq);
            uint32_t sz = ok ? 16u : 0u;
            asm volatile("cp.async.cg.shared.global [%0], [%1], 16, %2;"
                         :: "r"(sa), "l"(ga), "r"(sz) : "memory");
        }
        {
            const __half* gb = W + (size_t)(bn + row) * 320 + k0 + cq;
            uint32_t sb = smem_u32(dst + TILE_H + row * SROW_H + cq);
            asm volatile("cp.async.cg.shared.global [%0], [%1], 16;"
                         :: "r"(sb), "l"(gb) : "memory");
        }
    }
}

__global__ __launch_bounds__(128, 2)
void gemm1_h(const __half* __restrict__ X, const __half* __restrict__ W,
             float* __restrict__ C) {
    extern __shared__ __half smh[];
    const int tid  = threadIdx.x;
    const int wid  = tid >> 5;
    const int lane = tid & 31;
    const int wm = wid & 1, wn = wid >> 1;
    const int g  = lane >> 2, c4 = lane & 3;
    const int bm = blockIdx.y * 128;      // grid: x = 8 col tiles (fast), y = 512 row tiles
    const int bn = blockIdx.x * 128;
    const int KC = 10;

    float acc[4][8][4];
#pragma unroll
    for (int mt = 0; mt < 4; mt++)
#pragma unroll
        for (int nt = 0; nt < 8; nt++)
#pragma unroll
            for (int i = 0; i < 4; i++) acc[mt][nt][i] = 0.f;

    g1_load(smh, X, W, bm, bn, 0, tid);
    asm volatile("cp.async.commit_group;" ::: "memory");
    g1_load(smh + STAGE_H, X, W, bm, bn, 32, tid);
    asm volatile("cp.async.commit_group;" ::: "memory");
    asm volatile("cp.async.wait_group 1;" ::: "memory");
    __syncthreads();

    int st = 0;
    for (int ci = 0; ci < KC; ci++) {
        const __half* As = smh + (size_t)st * STAGE_H;
        const __half* Bs = As + TILE_H;
#pragma unroll
        for (int ks = 0; ks < 2; ks++) {
            const int kb = ks * 16;
            uint32_t a[4][4];
#pragma unroll
            for (int mt = 0; mt < 4; mt++) {
                const __half* ap = As + (wm * 64 + mt * 16 + g) * SROW_H + kb + 2 * c4;
                a[mt][0] = *(const uint32_t*)ap;
                a[mt][1] = *(const uint32_t*)(ap + 8 * SROW_H);
                a[mt][2] = *(const uint32_t*)(ap + 8);
                a[mt][3] = *(const uint32_t*)(ap + 8 * SROW_H + 8);
            }
            uint32_t b[8][2];
#pragma unroll
            for (int nt = 0; nt < 8; nt++) {
                const __half* bp = Bs + (wn * 64 + nt * 8 + g) * SROW_H + kb + 2 * c4;
                b[nt][0] = *(const uint32_t*)bp;
                b[nt][1] = *(const uint32_t*)(bp + 8);
            }
#pragma unroll
            for (int mt = 0; mt < 4; mt++)
#pragma unroll
                for (int nt = 0; nt < 8; nt++)
                    HMMA(acc[mt][nt], a[mt][0], a[mt][1], a[mt][2], a[mt][3],
                         b[nt][0], b[nt][1]);
        }
        if (ci + 2 < KC) {
            int sn = st + 2; if (sn >= 3) sn -= 3;
            g1_load(smh + (size_t)sn * STAGE_H, X, W, bm, bn, (ci + 2) * 32, tid);
            asm volatile("cp.async.commit_group;" ::: "memory");
            asm volatile("cp.async.wait_group 1;" ::: "memory");
        } else {
            asm volatile("cp.async.wait_group 0;" ::: "memory");
        }
        __syncthreads();
        if (++st == 3) st = 0;
    }

#pragma unroll
    for (int mt = 0; mt < 4; mt++) {
        const int row = bm + wm * 64 + mt * 16 + g;
#pragma unroll
        for (int nt = 0; nt < 8; nt++) {
            const int col = bn + wn * 64 + nt * 8 + 2 * c4;
            if (row < NN)
                *(float2*)&C[(size_t)row * 1024 + col] = make_float2(acc[mt][nt][0], acc[mt][nt][1]);
            if (row + 8 < NN)
                *(float2*)&C[(size_t)(row + 8) * 1024 + col] = make_float2(acc[mt][nt][2], acc[mt][nt][3]);
        }
    }
}

// ============================ merged per-level GEMM (fp16, d >= 7) ============================
// grid.x flat tiles: t < (S/128)*6 -> iou tile (A = hl16+hr16, B = WIOUh, C = PIOU, ldc 768)
//                    else          -> f tile   (A = h16 child rows, B = WFh, C = PF, ldc 256)
// K = 256 (8 chunks of 32 halves). S multiple of 128 -> no guards.
__global__ __launch_bounds__(256, 2)
void level_gemm_h(int S, int sc, int tiles_m_iou) {
    extern __shared__ __half smh[];

    const int tid  = threadIdx.x;
    const int wid  = tid >> 5;
    const int lane = tid & 31;
    const int wm = wid & 3, wn = wid >> 2;
    const int g  = lane >> 2, c4 = lane & 3;

    int t = blockIdx.x;
    const bool is_iou = (t < tiles_m_iou * 6);
    int tm, tn, ldc;
    const __half* Bsrc;
    float* C;
    if (is_iou) { tm = t / 6; tn = t - tm * 6; Bsrc = g_WIOUh + (size_t)tn * 128 * 256; C = g_PIOU; ldc = 768; }
    else { int t2 = t - tiles_m_iou * 6; tm = t2 >> 1; tn = t2 & 1; Bsrc = g_WFh + (size_t)tn * 128 * 256; C = g_PF; ldc = 256; }
    const int bm = tm * 128;

    const int r  = tid >> 1;           // 0..127 (A/B staging row)
    const int hq = (tid & 1) * 16;     // half offset 0 or 16

    float acc[2][8][4];
#pragma unroll
    for (int mt = 0; mt < 2; mt++)
#pragma unroll
        for (int nt = 0; nt < 8; nt++)
#pragma unroll
            for (int i = 0; i < 4; i++) acc[mt][nt][i] = 0.f;

    uint4 ua0, ua1;

#define LGH_LOAD_A(ci)                                                                    \
    do {                                                                                  \
        const int k0 = (ci) * 32;                                                         \
        if (is_iou) {                                                                     \
            const __half* pl = g_H16 + (size_t)(sc + 2 * (bm + r)) * 256 + k0 + hq;       \
            const __half* pr = pl + 256;                                                  \
            uint4 l0 = *(const uint4*)pl, l1 = *(const uint4*)(pl + 8);                   \
            uint4 r0_ = *(const uint4*)pr, r1_ = *(const uint4*)(pr + 8);                 \
            ua0.x = hadd2u(l0.x, r0_.x); ua0.y = hadd2u(l0.y, r0_.y);                     \
            ua0.z = hadd2u(l0.z, r0_.z); ua0.w = hadd2u(l0.w, r0_.w);                     \
            ua1.x = hadd2u(l1.x, r1_.x); ua1.y = hadd2u(l1.y, r1_.y);                     \
            ua1.z = hadd2u(l1.z, r1_.z); ua1.w = hadd2u(l1.w, r1_.w);                     \
        } else {                                                                          \
            const __half* p = g_H16 + (size_t)(sc + bm + r) * 256 + k0 + hq;              \
            ua0 = *(const uint4*)p; ua1 = *(const uint4*)(p + 8);                         \
        }                                                                                 \
    } while (0)

#define LGH_STORE_A(As)                                                                   \
    do {                                                                                  \
        *(uint4*)&(As)[r * SROW_H + hq]     = ua0;                                        \
        *(uint4*)&(As)[r * SROW_H + hq + 8] = ua1;                                        \
    } while (0)

#define LGH_CPASYNC_B(ci, Bs)                                                             \
    do {                                                                                  \
        const int k0 = (ci) * 32;                                                         \
        const __half* gb = Bsrc + (size_t)r * 256 + k0 + hq;                              \
        uint32_t sb = smem_u32(&(Bs)[r * SROW_H + hq]);                                   \
        asm volatile("cp.async.cg.shared.global [%0], [%1], 16;" :: "r"(sb), "l"(gb) : "memory"); \
        asm volatile("cp.async.cg.shared.global [%0], [%1], 16;" :: "r"(sb + 16u), "l"(gb + 8) : "memory"); \
    } while (0)

    // prologue: chunk 0
    LGH_LOAD_A(0);
    LGH_CPASYNC_B(0, smh + TILE_H);
    asm volatile("cp.async.commit_group;" ::: "memory");
    LGH_STORE_A(smh);
    asm volatile("cp.async.wait_group 0;" ::: "memory");
    __syncthreads();

    for (int ci = 0; ci < 8; ci++) {
        __half* bufn = smh + (size_t)((ci + 1) & 1) * STAGE_H;
        if (ci + 1 < 8) {
            LGH_LOAD_A(ci + 1);
            LGH_CPASYNC_B(ci + 1, bufn + TILE_H);
            asm volatile("cp.async.commit_group;" ::: "memory");
        }
        const __half* As = smh + (size_t)(ci & 1) * STAGE_H;
        const __half* Bs = As + TILE_H;
#pragma unroll
        for (int ks = 0; ks < 2; ks++) {
            const int kb = ks * 16;
            uint32_t a[2][4];
#pragma unroll
            for (int mt = 0; mt < 2; mt++) {
                const __half* ap = As + (wm * 32 + mt * 16 + g) * SROW_H + kb + 2 * c4;
                a[mt][0] = *(const uint32_t*)ap;
                a[mt][1] = *(const uint32_t*)(ap + 8 * SROW_H);
                a[mt][2] = *(const uint32_t*)(ap + 8);
                a[mt][3] = *(const uint32_t*)(ap + 8 * SROW_H + 8);
            }
            uint32_t b[8][2];
#pragma unroll
            for (int nt = 0; nt < 8; nt++) {
                const __half* bp = Bs + (wn * 64 + nt * 8 + g) * SROW_H + kb + 2 * c4;
                b[nt][0] = *(const uint32_t*)bp;
                b[nt][1] = *(const uint32_t*)(bp + 8);
            }
#pragma unroll
            for (int mt = 0; mt < 2; mt++)
#pragma unroll
                for (int nt = 0; nt < 8; nt++)
                    HMMA(acc[mt][nt], a[mt][0], a[mt][1], a[mt][2], a[mt][3],
                         b[nt][0], b[nt][1]);
        }
        __syncthreads();
        if (ci + 1 < 8) {
            LGH_STORE_A(bufn);
            asm volatile("cp.async.wait_group 0;" ::: "memory");
            __syncthreads();
        }
    }

#pragma unroll
    for (int mt = 0; mt < 2; mt++) {
        const int row = bm + wm * 32 + mt * 16 + g;
#pragma unroll
        for (int nt = 0; nt < 8; nt++) {
            const int col = tn * 128 + wn * 64 + nt * 8 + 2 * c4;
            *(float2*)&C[(size_t)row * ldc + col] = make_float2(acc[mt][nt][0], acc[mt][nt][1]);
            *(float2*)&C[(size_t)(row + 8) * ldc + col] = make_float2(acc[mt][nt][2], acc[mt][nt][3]);
        }
    }
#undef LGH_LOAD_A
#undef LGH_STORE_A
#undef LGH_CPASYNC_B
}

// ============================ epilogues ============================
__device__ __forceinline__ float sigmoidf_(float x) { return __fdividef(1.f, 1.f + __expf(-x)); }
__device__ __forceinline__ float ftanh_(float x) {
    float t = __expf(2.f * x);
    return 1.f - __fdividef(2.f, t + 1.f);
}
__device__ __forceinline__ float4 f4add(float4 a, float4 b) {
    return make_float4(a.x + b.x, a.y + b.y, a.z + b.z, a.w + b.w);
}
__device__ __forceinline__ void store_h16(int n, int q, float4 hn) {
    __half2 lo = __floats2half2_rn(hn.x, hn.y);
    __half2 hi = __floats2half2_rn(hn.z, hn.w);
    uint2 v = make_uint2(*reinterpret_cast<uint32_t*>(&lo), *reinterpret_cast<uint32_t*>(&hi));
    *(uint2*)&g_H16[(size_t)n * 256 + q] = v;
}

__global__ void leaf_epi(float* __restrict__ c, float* __restrict__ h) {
    const int j = threadIdx.x >> 6;
    const int q = (threadIdx.x & 63) * 4;
    const int n = LEAF_START + blockIdx.x * 4 + j;
    const float* pre = g_PRE + (size_t)n * 1024;
    float4 pi = f4add(*(const float4*)&pre[q],        *(const float4*)&g_BIO[q]);
    float4 po = f4add(*(const float4*)&pre[256 + q],  *(const float4*)&g_BIO[256 + q]);
    float4 pu = f4add(*(const float4*)&pre[512 + q],  *(const float4*)&g_BIO[512 + q]);
    float4 cn, hn;
#define GATE(X) do { \
        float iv = sigmoidf_(pi.X), ov = sigmoidf_(po.X), uv = ftanh_(pu.X); \
        float cv = iv * uv; cn.X = cv; hn.X = ov * ftanh_(cv); } while (0)
    GATE(x); GATE(y); GATE(z); GATE(w);
#undef GATE
    *(float4*)&c[(size_t)n * NMEM + q] = cn;
    *(float4*)&h[(size_t)n * NMEM + q] = hn;
    store_h16(n, q, hn);
}

__global__ void level_epi(float* __restrict__ c, float* __restrict__ h,
                          int start, int sc, int S) {
    const int j = threadIdx.x >> 6;
    const int q = (threadIdx.x & 63) * 4;
    const int r = blockIdx.x * 4 + j;
    const int n = start + r;
    const float* pre = g_PRE + (size_t)n * 1024;
    const float* piou = g_PIOU + (size_t)r * 768;
    float4 pi = f4add(f4add(*(const float4*)&piou[q],       *(const float4*)&pre[q]),       *(const float4*)&g_BIO[q]);
    float4 po = f4add(f4add(*(const float4*)&piou[256 + q], *(const float4*)&pre[256 + q]), *(const float4*)&g_BIO[256 + q]);
    float4 pu = f4add(f4add(*(const float4*)&piou[512 + q], *(const float4*)&pre[512 + q]), *(const float4*)&g_BIO[512 + q]);
    float4 fx = f4add(*(const float4*)&pre[768 + q], *(const float4*)&g_BF[q]);
    float4 pfl = f4add(*(const float4*)&g_PF[(size_t)(2 * r) * 256 + q], fx);
    float4 pfr = f4add(*(const float4*)&g_PF[(size_t)(2 * r + 1) * 256 + q], fx);
    float4 cl = *(const float4*)&c[(size_t)(sc + 2 * r) * NMEM + q];
    float4 cr = *(const float4*)&c[(size_t)(sc + 2 * r + 1) * NMEM + q];
    float4 cn, hn;
#define GATE(X) do { \
        float iv = sigmoidf_(pi.X), ov = sigmoidf_(po.X), uv = ftanh_(pu.X); \
        float fl = sigmoidf_(pfl.X), fr = sigmoidf_(pfr.X); \
        float cv = iv * uv + fl * cl.X + fr * cr.X; \
        cn.X = cv; hn.X = ov * ftanh_(cv); } while (0)
    GATE(x); GATE(y); GATE(z); GATE(w);
#undef GATE
    *(float4*)&c[(size_t)n * NMEM + q] = cn;
    *(float4*)&h[(size_t)n * NMEM + q] = hn;
    store_h16(n, q, hn);
}

// ============================ fused small levels (d <= 6, S <= 64) ============================
// One CTA per node. Thread t computes iou outputs {t, t+256, t+512} and f outputs {t} for
// both children -> owns exactly the gates for m = t. GEMM + epilogue fused, no scratch.
__global__ __launch_bounds__(256)
void fused_small(float* __restrict__ c, float* __restrict__ h, int start, int sc) {
    __shared__ float s_hsum[256], s_hl[256], s_hr[256];
    const int r = blockIdx.x, t = threadIdx.x;
    const int n = start + r;
    const int lc = sc + 2 * r;
    float hl = h[(size_t)lc * NMEM + t];
    float hr = h[(size_t)(lc + 1) * NMEM + t];
    s_hl[t] = hl; s_hr[t] = hr; s_hsum[t] = hl + hr;
    __syncthreads();

    const __half* w0 = g_WIOUh + (size_t)t * 256;
    const __half* w1 = w0 + 256 * 256;
    const __half* w2 = w1 + 256 * 256;
    const __half* wf = g_WFh + (size_t)t * 256;

    float di = 0.f, dq = 0.f, du = 0.f, dfl = 0.f, dfr = 0.f;
#pragma unroll 4
    for (int k = 0; k < 256; k += 8) {
        uint4 u0 = *(const uint4*)&w0[k];
        uint4 u1 = *(const uint4*)&w1[k];
        uint4 u2 = *(const uint4*)&w2[k];
        uint4 uf = *(const uint4*)&wf[k];
#pragma unroll
        for (int p = 0; p < 4; p++) {
            uint32_t b0 = (&u0.x)[p], b1 = (&u1.x)[p], b2 = (&u2.x)[p], bf = (&uf.x)[p];
            float2 f0 = __half22float2(*reinterpret_cast<__half2*>(&b0));
            float2 f1 = __half22float2(*reinterpret_cast<__half2*>(&b1));
            float2 f2 = __half22float2(*reinterpret_cast<__half2*>(&b2));
            float2 ff = __half22float2(*reinterpret_cast<__half2*>(&bf));
            float hs0 = s_hsum[k + 2 * p], hs1 = s_hsum[k + 2 * p + 1];
            float l0 = s_hl[k + 2 * p],   l1 = s_hl[k + 2 * p + 1];
            float r0 = s_hr[k + 2 * p],   r1 = s_hr[k + 2 * p + 1];
            di  = fmaf(f0.x, hs0, fmaf(f0.y, hs1, di));
            dq  = fmaf(f1.x, hs0, fmaf(f1.y, hs1, dq));
            du  = fmaf(f2.x, hs0, fmaf(f2.y, hs1, du));
            dfl = fmaf(ff.x, l0,  fmaf(ff.y, l1,  dfl));
            dfr = fmaf(ff.x, r0,  fmaf(ff.y, r1,  dfr));
        }
    }

    const float* pre = g_PRE + (size_t)n * 1024;
    float iv = sigmoidf_(di + pre[t]       + g_BIO[t]);
    float ov = sigmoidf_(dq + pre[256 + t] + g_BIO[256 + t]);
    float uv = ftanh_(   du + pre[512 + t] + g_BIO[512 + t]);
    float fx = pre[768 + t] + g_BF[t];
    float fl = sigmoidf_(dfl + fx);
    float fr = sigmoidf_(dfr + fx);
    float cl = c[(size_t)lc * NMEM + t];
    float cr = c[(size_t)(lc + 1) * NMEM + t];
    float cn = iv * uv + fl * cl + fr * cr;
    float hn = ov * ftanh_(cn);
    c[(size_t)n * NMEM + t] = cn;
    h[(size_t)n * NMEM + t] = hn;
    g_H16[(size_t)n * 256 + t] = __float2half_rn(hn);
}

// ============================ launcher ============================
extern "C" void kernel_launch(void* const* d_in, const int* in_sizes, int n_in,
                              void* d_out, int out_size) {
    const float* inputs = (const float*)d_in[0];
    const float* W_ioux = (const float*)d_in[1];
    const float* b_ioux = (const float*)d_in[2];
    const float* W_iouh = (const float*)d_in[3];
    const float* b_iouh = (const float*)d_in[4];
    const float* W_fx   = (const float*)d_in[5];
    const float* b_fx   = (const float*)d_in[6];
    const float* W_fh   = (const float*)d_in[7];
    const float* b_fh   = (const float*)d_in[8];
    (void)in_sizes; (void)n_in; (void)out_size;

    float* c = (float*)d_out;                   // out[0] = c  [N,256]
    float* h = c + (size_t)NN * NMEM;           // out[1] = h  [N,256]

    float* pPRE;
    __half *pX16, *pW1h;
    cudaGetSymbolAddress((void**)&pPRE, g_PRE);
    cudaGetSymbolAddress((void**)&pX16, g_X16);
    cudaGetSymbolAddress((void**)&pW1h, g_W1h);

    const int SMEM1 = 3 * STAGE_H * 2;   // 61440 B (3-stage fp16)
    const int SMEML = 2 * STAGE_H * 2;   // 40960 B (2-stage fp16)
    cudaFuncSetAttribute(gemm1_h,      cudaFuncAttributeMaxDynamicSharedMemorySize, SMEM1);
    cudaFuncSetAttribute(level_gemm_h, cudaFuncAttributeMaxDynamicSharedMemorySize, SMEML);

    conv_x<<<(NN * 160 + 255) / 256, 256>>>(inputs);
    build_w1h<<<(1024 * 320 + 255) / 256, 256>>>(W_ioux, W_fx);
    build_misch<<<(263168 + 255) / 256, 256>>>(W_iouh, W_fh, b_ioux, b_iouh, b_fx, b_fh);

    // gemm1: PRE = X16 @ W1h^T  (M=65535, K=320, N=1024)
    {
        dim3 grd(8, 512);
        gemm1_h<<<grd, 128, SMEM1>>>(pX16, pW1h, pPRE);
    }

    // leaves (depth 15)
    leaf_epi<<<8192, 256>>>(c, h);

    // big internal levels (S multiple of 128)
    for (int d = 14; d >= 7; --d) {
        const int S = 1 << d;
        const int start = S - 1;
        const int sc = 2 * S - 1;
        const int tiles_m_iou = S / 128;
        const int gx = tiles_m_iou * 6 + (2 * S / 128) * 2;
        level_gemm_h<<<gx, 256, SMEML>>>(S, sc, tiles_m_iou);
        level_epi<<<S / 4, 256>>>(c, h, start, sc, S);
    }

    // small levels (d <= 6): fused GEMM + epilogue, one launch per level
    for (int d = 6; d >= 0; --d) {
        const int S = 1 << d;
        fused_small<<<S, 256>>>(c, h, S - 1, 2 * S - 1);
    }
}